// round 3
// baseline (speedup 1.0000x reference)
#include <cuda_runtime.h>
#include <math.h>

#define NQ 512
#define NC 65536
#define DIN 768

typedef unsigned long long u64;

// Scratch (static device globals).
// Corpus features, SoA rows x NC: 0..31 e, 32..47 h, 48..63 s, 64 yn
__device__ float g_cfeatT[65 * NC];
// Query features: rows 0..63 as above, 64 xn, 65 beta, 66 w0, 67 w1*ln2^2, 68 w2
__device__ float g_qfeatT[69 * NQ];

// ---------------- packed f32x2 helpers ----------------
__device__ __forceinline__ u64 pk2(float a, float b) {
    u64 r; asm("mov.b64 %0,{%1,%2};" : "=l"(r) : "f"(a), "f"(b)); return r;
}
__device__ __forceinline__ u64 dup2(float a) {
    u64 r; asm("mov.b64 %0,{%1,%1};" : "=l"(r) : "f"(a)); return r;
}
__device__ __forceinline__ float2 up2(u64 v) {
    float2 f; asm("mov.b64 {%0,%1},%2;" : "=f"(f.x), "=f"(f.y) : "l"(v)); return f;
}
__device__ __forceinline__ u64 f2fma(u64 a, u64 b, u64 c) {
    u64 d; asm("fma.rn.f32x2 %0,%1,%2,%3;" : "=l"(d) : "l"(a), "l"(b), "l"(c)); return d;
}
__device__ __forceinline__ u64 f2mul(u64 a, u64 b) {
    u64 d; asm("mul.rn.f32x2 %0,%1,%2;" : "=l"(d) : "l"(a), "l"(b)); return d;
}
__device__ __forceinline__ u64 f2add(u64 a, u64 b) {
    u64 d; asm("add.rn.f32x2 %0,%1,%2;" : "=l"(d) : "l"(a), "l"(b)); return d;
}
// ---------------- MUFU helpers ----------------
__device__ __forceinline__ float f_rcp(float x)  { float r; asm("rcp.approx.f32 %0,%1;"   : "=f"(r) : "f"(x)); return r; }
__device__ __forceinline__ float f_sqrt(float x) { float r; asm("sqrt.approx.f32 %0,%1;"  : "=f"(r) : "f"(x)); return r; }
__device__ __forceinline__ float f_rsq(float x)  { float r; asm("rsqrt.approx.f32 %0,%1;" : "=f"(r) : "f"(x)); return r; }
__device__ __forceinline__ float f_lg2(float x)  { float r; asm("lg2.approx.f32 %0,%1;"   : "=f"(r) : "f"(x)); return r; }

// ===========================================================================
// Projection: 256 rows x 64 dims per block, 256 threads, 8x8 per thread (FFMA2)
// ===========================================================================
__global__ __launch_bounds__(256, 1) void proj256_kernel(
    const float* __restrict__ X,
    const float* __restrict__ We, const float* __restrict__ be,
    const float* __restrict__ Wh, const float* __restrict__ bh,
    const float* __restrict__ Ws, const float* __restrict__ bs,
    const float* __restrict__ scale_p,
    float* __restrict__ featT, int fstride, int is_query)
{
    __shared__ __align__(16) float xs[16][260];
    __shared__ __align__(16) float ws[16][68];

    const int tid = threadIdx.x;
    const int row0 = blockIdx.x * 256;
    const int tcol = tid & 7;          // dim group: d0 = tcol*8
    const int trow = tid >> 3;         // row group: r0 = trow*8
    const int d0 = tcol * 8;
    const int r0 = trow * 8;

    // staging mapping
    const int sr  = tid >> 2;          // 0..63
    const int skc = (tid & 3) * 4;     // 0,4,8,12
    const float* Xbase = X + (size_t)(row0 + sr) * DIN + skc;
    const float* Wrow;
    if (sr < 32)      Wrow = We + sr * DIN + skc;
    else if (sr < 48) Wrow = Wh + (sr - 32) * DIN + skc;
    else              Wrow = Ws + (sr - 48) * DIN + skc;

    float4 px[4], pw;
#pragma unroll
    for (int g = 0; g < 4; g++) px[g] = *(const float4*)(Xbase + (size_t)g * 64 * DIN);
    pw = *(const float4*)(Wrow);

    u64 acc[4][8];
#pragma unroll
    for (int i = 0; i < 4; i++)
#pragma unroll
        for (int j = 0; j < 8; j++) acc[i][j] = 0ull;

    for (int k0 = 0; k0 < DIN; k0 += 16) {
        __syncthreads();
#pragma unroll
        for (int g = 0; g < 4; g++) {
            const int r = sr + g * 64;
            xs[skc + 0][r] = px[g].x; xs[skc + 1][r] = px[g].y;
            xs[skc + 2][r] = px[g].z; xs[skc + 3][r] = px[g].w;
        }
        ws[skc + 0][sr] = pw.x; ws[skc + 1][sr] = pw.y;
        ws[skc + 2][sr] = pw.z; ws[skc + 3][sr] = pw.w;
        __syncthreads();
        if (k0 + 16 < DIN) {
#pragma unroll
            for (int g = 0; g < 4; g++)
                px[g] = *(const float4*)(Xbase + (size_t)g * 64 * DIN + k0 + 16);
            pw = *(const float4*)(Wrow + k0 + 16);
        }
#pragma unroll
        for (int k = 0; k < 16; k++) {
            float4 a0 = *(const float4*)&xs[k][r0];
            float4 a1 = *(const float4*)&xs[k][r0 + 4];
            u64 a2[4] = { pk2(a0.x, a0.y), pk2(a0.z, a0.w),
                          pk2(a1.x, a1.y), pk2(a1.z, a1.w) };
            float4 b0 = *(const float4*)&ws[k][d0];
            float4 b1 = *(const float4*)&ws[k][d0 + 4];
            float bb[8] = { b0.x, b0.y, b0.z, b0.w, b1.x, b1.y, b1.z, b1.w };
#pragma unroll
            for (int j = 0; j < 8; j++) {
                u64 bd = dup2(bb[j]);
#pragma unroll
                for (int i = 0; i < 4; i++)
                    acc[i][j] = f2fma(a2[i], bd, acc[i][j]);
            }
        }
    }

    // -------- epilogue: bias, per-row segment norms via shuffle --------
    const float sc = *scale_p;
    float bias[8];
#pragma unroll
    for (int j = 0; j < 8; j++) {
        int d = d0 + j;
        bias[j] = (d < 32) ? be[d] : (d < 48) ? bh[d - 32] : bs[d - 48];
    }
    const int seg = (tcol < 4) ? 0 : (tcol < 6) ? 1 : 2;  // e / h / s
    float f8[8];
#pragma unroll
    for (int i = 0; i < 8; i++) {
        const int i2 = i >> 1, half = i & 1;
        float ssq = 0.f;
#pragma unroll
        for (int j = 0; j < 8; j++) {
            float2 fp = up2(acc[i2][j]);
            float v = (half ? fp.y : fp.x) + bias[j];
            if (seg == 1) v *= sc;
            ssq = fmaf(v, v, ssq);
        }
        float o1 = __shfl_xor_sync(0xffffffffu, ssq, 1); ssq += o1;
        float o2 = __shfl_xor_sync(0xffffffffu, ssq, 2);
        if (tcol < 4) ssq += o2;

        float f;
        if (seg == 1) {
            float n = fmaxf(f_sqrt(ssq), 1e-15f);
            float th = tanhf(n);
            f = th * f_rcp(n);
            if (tcol == 4) {
                float th2 = th * th;
                featT[(size_t)64 * fstride + row0 + r0 + i] = th2;
                if (is_query)
                    featT[(size_t)65 * fstride + row0 + r0 + i] = 1.f - th2;
            }
        } else {
            f = f_rsq(ssq);
        }
        f8[i] = f;
    }
    // pass 2: write features transposed (float4 along rows)
#pragma unroll
    for (int j = 0; j < 8; j++) {
        const int d = d0 + j;
        float v[8];
#pragma unroll
        for (int i = 0; i < 8; i++) {
            const int i2 = i >> 1, half = i & 1;
            float2 fp = up2(acc[i2][j]);
            float x = (half ? fp.y : fp.x) + bias[j];
            if (seg == 1) x *= sc;
            v[i] = x * f8[i];
        }
        float* dst = featT + (size_t)d * fstride + row0 + r0;
        *(float4*)(dst)     = make_float4(v[0], v[1], v[2], v[3]);
        *(float4*)(dst + 4) = make_float4(v[4], v[5], v[6], v[7]);
    }
}

// ===========================================================================
// Fused weight MLP: relu(x W1^T + b1) W2^T + b2 -> softplus -> qfT rows 66..68
// Block: 256 query rows, 256 threads.
// ===========================================================================
__global__ __launch_bounds__(256, 1) void mlpq_kernel(
    const float* __restrict__ X, const float* __restrict__ W1,
    const float* __restrict__ b1, const float* __restrict__ W2,
    const float* __restrict__ b2, float* __restrict__ qfT)
{
    __shared__ __align__(16) float sbuf[256 * 33];
    float (*xs)[260] = (float(*)[260])sbuf;
    float (*ws1)[36] = (float(*)[36])(sbuf + 16 * 260);
    float (*ys)[33]  = (float(*)[33])sbuf;

    const int tid = threadIdx.x;
    const int row0 = blockIdx.x * 256;
    const int tcol = tid & 3;           // d0 = tcol*8 (0..24)
    const int trow = tid >> 2;          // r0 = trow*4
    const int d0 = tcol * 8;
    const int r0 = trow * 4;

    const int sr  = tid >> 2;
    const int skc = (tid & 3) * 4;
    const float* Xbase = X + (size_t)(row0 + sr) * DIN + skc;
    const float* W1p = (tid < 128) ? (W1 + (tid >> 2) * DIN + skc) : W1;

    float4 px[4], pw;
#pragma unroll
    for (int g = 0; g < 4; g++) px[g] = *(const float4*)(Xbase + (size_t)g * 64 * DIN);
    pw = (tid < 128) ? *(const float4*)(W1p) : make_float4(0.f, 0.f, 0.f, 0.f);

    u64 acc[2][8];
#pragma unroll
    for (int i = 0; i < 2; i++)
#pragma unroll
        for (int j = 0; j < 8; j++) acc[i][j] = 0ull;

    for (int k0 = 0; k0 < DIN; k0 += 16) {
        __syncthreads();
#pragma unroll
        for (int g = 0; g < 4; g++) {
            const int r = sr + g * 64;
            xs[skc + 0][r] = px[g].x; xs[skc + 1][r] = px[g].y;
            xs[skc + 2][r] = px[g].z; xs[skc + 3][r] = px[g].w;
        }
        if (tid < 128) {
            const int sd = tid >> 2;
            ws1[skc + 0][sd] = pw.x; ws1[skc + 1][sd] = pw.y;
            ws1[skc + 2][sd] = pw.z; ws1[skc + 3][sd] = pw.w;
        }
        __syncthreads();
        if (k0 + 16 < DIN) {
#pragma unroll
            for (int g = 0; g < 4; g++)
                px[g] = *(const float4*)(Xbase + (size_t)g * 64 * DIN + k0 + 16);
            if (tid < 128) pw = *(const float4*)(W1p + k0 + 16);
        }
#pragma unroll
        for (int k = 0; k < 16; k++) {
            float4 a0 = *(const float4*)&xs[k][r0];
            u64 a2[2] = { pk2(a0.x, a0.y), pk2(a0.z, a0.w) };
            float4 b0 = *(const float4*)&ws1[k][d0];
            float4 b1v = *(const float4*)&ws1[k][d0 + 4];
            float bb[8] = { b0.x, b0.y, b0.z, b0.w, b1v.x, b1v.y, b1v.z, b1v.w };
#pragma unroll
            for (int j = 0; j < 8; j++) {
                u64 bd = dup2(bb[j]);
                acc[0][j] = f2fma(a2[0], bd, acc[0][j]);
                acc[1][j] = f2fma(a2[1], bd, acc[1][j]);
            }
        }
    }
    __syncthreads();   // stage buffers dead; ys overlaps
#pragma unroll
    for (int i = 0; i < 4; i++) {
        const int i2 = i >> 1, half = i & 1;
#pragma unroll
        for (int j = 0; j < 8; j++) {
            float2 fp = up2(acc[i2][j]);
            float v = (half ? fp.y : fp.x) + b1[d0 + j];
            ys[r0 + i][d0 + j] = fmaxf(v, 0.f);
        }
    }
    __syncthreads();

    // layer 2 + softplus: one query per thread
    const int q = tid;
    float z0 = b2[0], z1 = b2[1], z2 = b2[2];
#pragma unroll
    for (int k = 0; k < 32; k++) {
        float y = ys[q][k];
        z0 = fmaf(y, __ldg(W2 + k),      z0);
        z1 = fmaf(y, __ldg(W2 + 32 + k), z1);
        z2 = fmaf(y, __ldg(W2 + 64 + k), z2);
    }
    float sp0 = fmaxf(z0, 0.f) + log1pf(expf(-fabsf(z0)));
    float sp1 = fmaxf(z1, 0.f) + log1pf(expf(-fabsf(z1)));
    float sp2 = fmaxf(z2, 0.f) + log1pf(expf(-fabsf(z2)));
    qfT[(size_t)66 * NQ + row0 + q] = sp0;
    qfT[(size_t)67 * NQ + row0 + q] = sp1 * 0.4804530139182014f;  // fold ln2^2
    qfT[(size_t)68 * NQ + row0 + q] = sp2;
}

// ===========================================================================
// Pairwise kernel: 128q x 128c tile, 256 threads, 8x8 per thread, 3 phases
// ===========================================================================
__global__ __launch_bounds__(256, 1) void pair_kernel(
    const float* __restrict__ qfT, const float* __restrict__ cfT,
    float* __restrict__ out)
{
    __shared__ __align__(16) float bq[32][128];
    __shared__ __align__(16) float bc[32][128];
    __shared__ float qxn[128], qbt[128], qw0[128], qw1[128], qw2[128], cyn[128];

    const int tid = threadIdx.x;
    const int q0 = blockIdx.y * 128;
    const int c0 = blockIdx.x * 128;
    const int ty = tid >> 4;   // q group: rows ty*8..
    const int tx = tid & 15;   // c group: cols tx*8..

    if (tid < 128) {
        qxn[tid] = qfT[(size_t)64 * NQ + q0 + tid];
        qbt[tid] = qfT[(size_t)65 * NQ + q0 + tid];
        qw0[tid] = qfT[(size_t)66 * NQ + q0 + tid];
        qw1[tid] = qfT[(size_t)67 * NQ + q0 + tid];
        qw2[tid] = qfT[(size_t)68 * NQ + q0 + tid];
    } else {
        const int r = tid - 128;
        cyn[r] = cfT[(size_t)64 * NC + c0 + r];
    }

    u64 tot[4][8];
    u64 acc[4][8];

    const u64 C1  = dup2(1.f);
    const u64 C2  = dup2(2.f);
    const u64 CM2 = dup2(-2.f);

    // ---- helper lambdas ----
    auto load_phase = [&](int off, int kd) {
        for (int idx = tid; idx < kd * 32; idx += 256) {
            const int k = idx >> 5;
            const int c = (idx & 31) * 4;
            *(float4*)&bq[k][c] = *(const float4*)&qfT[(size_t)(off + k) * NQ + q0 + c];
            *(float4*)&bc[k][c] = *(const float4*)&cfT[(size_t)(off + k) * NC + c0 + c];
        }
    };
    auto dot_phase = [&](int kd) {
#pragma unroll
        for (int i = 0; i < 4; i++)
#pragma unroll
            for (int j = 0; j < 8; j++) acc[i][j] = 0ull;
        for (int k = 0; k < kd; k++) {
            float4 a0 = *(const float4*)&bq[k][ty * 8];
            float4 a1 = *(const float4*)&bq[k][ty * 8 + 4];
            u64 a2[4] = { pk2(a0.x, a0.y), pk2(a0.z, a0.w),
                          pk2(a1.x, a1.y), pk2(a1.z, a1.w) };
            float4 b0 = *(const float4*)&bc[k][tx * 8];
            float4 b1v = *(const float4*)&bc[k][tx * 8 + 4];
            float bb[8] = { b0.x, b0.y, b0.z, b0.w, b1v.x, b1v.y, b1v.z, b1v.w };
#pragma unroll
            for (int j = 0; j < 8; j++) {
                u64 bd = dup2(bb[j]);
#pragma unroll
                for (int i = 0; i < 4; i++)
                    acc[i][j] = f2fma(a2[i], bd, acc[i][j]);
            }
        }
    };

    // ================= phase e (features 0..31) =================
    __syncthreads();
    load_phase(0, 32);
    __syncthreads();
    dot_phase(32);
#pragma unroll
    for (int i2 = 0; i2 < 4; i2++) {
        const int r = ty * 8 + 2 * i2;
        u64 w0p = pk2(qw0[r], qw0[r + 1]);
#pragma unroll
        for (int j = 0; j < 8; j++)
            tot[i2][j] = f2mul(w0p, f2fma(acc[i2][j], CM2, C2));
    }

    // ================= phase h (features 32..47) =================
    __syncthreads();
    load_phase(32, 16);
    __syncthreads();
    dot_phase(16);
#pragma unroll
    for (int i2 = 0; i2 < 4; i2++) {
        const int r = ty * 8 + 2 * i2;
        u64 xn2 = pk2(qxn[r], qxn[r + 1]);
        float bl = qbt[r], bh2 = qbt[r + 1];
        u64 nb2 = pk2(-2.f * bl, -2.f * bh2);
        u64 bb2 = pk2(bl * bl, bh2 * bh2);
        u64 w1p = pk2(qw1[r], qw1[r + 1]);
#pragma unroll
        for (int j = 0; j < 8; j++) {
            u64 ynd = dup2(cyn[tx * 8 + j]);
            u64 v = acc[i2][j];
            u64 s1 = f2fma(v, CM2, C1);                 // 1 - 2*dot
            u64 al = f2add(s1, ynd);                    // alpha
            u64 inner = f2fma(al, xn2, f2mul(nb2, v));  // a*xn - 2b*dot
            u64 num = f2fma(al, inner, f2mul(bb2, ynd));
            u64 den = f2fma(xn2, ynd, s1);
            float2 fn = up2(num), fd = up2(den);
            float t0 = f_sqrt(fmaxf(fn.x, 0.f)) * f_rcp(fd.x);
            float t1 = f_sqrt(fmaxf(fn.y, 0.f)) * f_rcp(fd.y);
            t0 = fminf(t0, 0.99999994f);
            t1 = fminf(t1, 0.99999994f);
            float g0 = f_lg2((1.f + t0) * f_rcp(1.f - t0));  // log2 of ratio
            float g1 = f_lg2((1.f + t1) * f_rcp(1.f - t1));
            tot[i2][j] = f2fma(w1p, pk2(g0 * g0, g1 * g1), tot[i2][j]);
        }
    }

    // ================= phase s (features 48..63) =================
    __syncthreads();
    load_phase(48, 16);
    __syncthreads();
    dot_phase(16);
    {
        const u64 CM1 = dup2(-1.f);
        const u64 c7 = dup2(-0.0012624911f), c6 = dup2(0.0066700901f);
        const u64 c5 = dup2(-0.0170881256f), c4 = dup2(0.0308918810f);
        const u64 c3 = dup2(-0.0501743046f), c2 = dup2(0.0889789874f);
        const u64 c1 = dup2(-0.2145988016f), c0 = dup2(1.5707963050f);
#pragma unroll
        for (int i2 = 0; i2 < 4; i2++) {
            const int r = ty * 8 + 2 * i2;
            u64 w2p = pk2(qw2[r], qw2[r + 1]);
#pragma unroll
            for (int j = 0; j < 8; j++) {
                u64 v = acc[i2][j];
                u64 av = v & 0x7FFFFFFF7FFFFFFFull;        // |d| packed
                u64 onem = f2fma(av, CM1, C1);             // 1-|d|
                float2 om = up2(onem);
                u64 sq2 = pk2(f_sqrt(fmaxf(om.x, 0.f)), f_sqrt(fmaxf(om.y, 0.f)));
                u64 p = c7;
                p = f2fma(p, av, c6); p = f2fma(p, av, c5);
                p = f2fma(p, av, c4); p = f2fma(p, av, c3);
                p = f2fma(p, av, c2); p = f2fma(p, av, c1);
                p = f2fma(p, av, c0);
                u64 rr = f2mul(sq2, p);                    // acos(|d|)
                float2 fr = up2(rr); float2 fv = up2(v);
                float a0 = (fv.x >= 0.f) ? fr.x : 3.14159274f - fr.x;
                float a1 = (fv.y >= 0.f) ? fr.y : 3.14159274f - fr.y;
                tot[i2][j] = f2fma(w2p, pk2(a0 * a0, a1 * a1), tot[i2][j]);
            }
        }
    }

    // ================= store -total =================
#pragma unroll
    for (int i2 = 0; i2 < 4; i2++) {
        float o0[8], o1[8];
#pragma unroll
        for (int j = 0; j < 8; j++) {
            float2 f = up2(tot[i2][j]);
            o0[j] = -f.x; o1[j] = -f.y;
        }
        const size_t rA = (size_t)(q0 + ty * 8 + 2 * i2) * NC + c0 + tx * 8;
        const size_t rB = rA + NC;
        *(float4*)(out + rA)     = make_float4(o0[0], o0[1], o0[2], o0[3]);
        *(float4*)(out + rA + 4) = make_float4(o0[4], o0[5], o0[6], o0[7]);
        *(float4*)(out + rB)     = make_float4(o1[0], o1[1], o1[2], o1[3]);
        *(float4*)(out + rB + 4) = make_float4(o1[4], o1[5], o1[6], o1[7]);
    }
}

// ===========================================================================
extern "C" void kernel_launch(void* const* d_in, const int* in_sizes, int n_in,
                              void* d_out, int out_size)
{
    const float* x_q = (const float*)d_in[0];
    const float* x_c = (const float*)d_in[1];
    const float* We  = (const float*)d_in[2];
    const float* be  = (const float*)d_in[3];
    const float* Wh  = (const float*)d_in[4];
    const float* bh  = (const float*)d_in[5];
    const float* Ws  = (const float*)d_in[6];
    const float* bs  = (const float*)d_in[7];
    const float* scl = (const float*)d_in[8];
    const float* W1  = (const float*)d_in[9];
    const float* b1  = (const float*)d_in[10];
    const float* W2  = (const float*)d_in[11];
    const float* b2  = (const float*)d_in[12];
    float* out = (float*)d_out;

    float *cfT, *qfT;
    cudaGetSymbolAddress((void**)&cfT, g_cfeatT);
    cudaGetSymbolAddress((void**)&qfT, g_qfeatT);

    proj256_kernel<<<NC / 256, 256>>>(x_c, We, be, Wh, bh, Ws, bs, scl, cfT, NC, 0);
    proj256_kernel<<<NQ / 256, 256>>>(x_q, We, be, Wh, bh, Ws, bs, scl, qfT, NQ, 1);
    mlpq_kernel<<<NQ / 256, 256>>>(x_q, W1, b1, W2, b2, qfT);
    pair_kernel<<<dim3(NC / 128, NQ / 128), 256>>>(qfT, cfT, out);
}

// round 4
// speedup vs baseline: 1.6696x; 1.6696x over previous
#include <cuda_runtime.h>
#include <math.h>

#define NQ 512
#define NC 65536
#define DIN 768

// Scratch (static device globals).
// Corpus features, SoA rows x NC: 0..31 e, 32..47 h, 48..63 s, 64 yn
__device__ float g_cfeatT[65 * NC];
// Query features: rows 0..63, 64 xn, 65 beta, 66 w0, 67 w1*ln2^2, 68 w2
__device__ float g_qfeatT[69 * NQ];
// Hidden relu layer for weight MLP
__device__ float g_qy[NQ * 32];

// ---------------- MUFU helpers ----------------
__device__ __forceinline__ float f_rcp(float x)  { float r; asm("rcp.approx.f32 %0,%1;"   : "=f"(r) : "f"(x)); return r; }
__device__ __forceinline__ float f_sqrt(float x) { float r; asm("sqrt.approx.f32 %0,%1;"  : "=f"(r) : "f"(x)); return r; }
__device__ __forceinline__ float f_lg2(float x)  { float r; asm("lg2.approx.f32 %0,%1;"   : "=f"(r) : "f"(x)); return r; }

// ---------------------------------------------------------------------------
// Projection kernel: 64 rows x 64 dims tile, prefetched K-chunked GEMM
// ---------------------------------------------------------------------------
__global__ __launch_bounds__(256) void proj64_kernel(
    const float* __restrict__ X,
    const float* __restrict__ We, const float* __restrict__ be,
    const float* __restrict__ Wh, const float* __restrict__ bh,
    const float* __restrict__ Ws, const float* __restrict__ bs,
    const float* __restrict__ scale_p,
    float* __restrict__ featT, int fstride, int is_query)
{
    __shared__ __align__(16) float xs[16][68];
    __shared__ __align__(16) float ws[16][68];
    __shared__ __align__(16) float psm[64][68];

    const int tid = threadIdx.x;
    const int r0 = (tid >> 4) * 4;   // row offset within 64-row tile
    const int d0 = (tid & 15) * 4;   // dim offset within 64 dims
    const int row0 = blockIdx.x * 64;

    const int lr = tid >> 2;         // 0..63 : row (for X) / dim (for W)
    const int lk = (tid & 3) * 4;    // k sub-offset 0,4,8,12

    const float* Xp = X + (size_t)(row0 + lr) * DIN + lk;
    const float* Wp;
    if (lr < 32)      Wp = We + lr * DIN + lk;
    else if (lr < 48) Wp = Wh + (lr - 32) * DIN + lk;
    else              Wp = Ws + (lr - 48) * DIN + lk;

    float acc[4][4] = {};

    float4 xv = *(const float4*)(Xp);
    float4 wv = *(const float4*)(Wp);

    for (int k0 = 0; k0 < DIN; k0 += 16) {
        __syncthreads();
        xs[lk + 0][lr] = xv.x; xs[lk + 1][lr] = xv.y;
        xs[lk + 2][lr] = xv.z; xs[lk + 3][lr] = xv.w;
        ws[lk + 0][lr] = wv.x; ws[lk + 1][lr] = wv.y;
        ws[lk + 2][lr] = wv.z; ws[lk + 3][lr] = wv.w;
        __syncthreads();
        if (k0 + 16 < DIN) {
            xv = *(const float4*)(Xp + k0 + 16);
            wv = *(const float4*)(Wp + k0 + 16);
        }
#pragma unroll
        for (int kk = 0; kk < 16; kk++) {
            float4 a4 = *(const float4*)&xs[kk][r0];
            float4 b4 = *(const float4*)&ws[kk][d0];
            float av[4] = {a4.x, a4.y, a4.z, a4.w};
            float bv[4] = {b4.x, b4.y, b4.z, b4.w};
#pragma unroll
            for (int i = 0; i < 4; i++)
#pragma unroll
                for (int j = 0; j < 4; j++)
                    acc[i][j] = fmaf(av[i], bv[j], acc[i][j]);
        }
    }
    __syncthreads();
#pragma unroll
    for (int i = 0; i < 4; i++)
#pragma unroll
        for (int j = 0; j < 4; j++) {
            int d = d0 + j;
            float bias = (d < 32) ? be[d] : (d < 48) ? bh[d - 32] : bs[d - 48];
            psm[r0 + i][d] = acc[i][j] + bias;
        }
    __syncthreads();

    if (tid < 64) {
        const int r = tid;
        const float sc = *scale_p;
        // e: normalize
        float s2 = 0.f;
#pragma unroll
        for (int k = 0; k < 32; k++) { float v = psm[r][k]; s2 = fmaf(v, v, s2); }
        float inv = 1.0f / sqrtf(s2);
#pragma unroll
        for (int k = 0; k < 32; k++) psm[r][k] *= inv;
        // h: expmap0((.) * scale)
        float h2 = 0.f;
#pragma unroll
        for (int k = 32; k < 48; k++) { float v = psm[r][k] * sc; psm[r][k] = v; h2 = fmaf(v, v, h2); }
        float n  = fmaxf(sqrtf(h2), 1e-15f);
        float th = tanhf(n);
        float fac = th / n;
#pragma unroll
        for (int k = 32; k < 48; k++) psm[r][k] *= fac;
        psm[r][64] = th * th;                       // yn (corpus) / xn (query)
        if (is_query) psm[r][65] = 1.0f - th * th;  // beta
        // s: normalize
        float s3 = 0.f;
#pragma unroll
        for (int k = 48; k < 64; k++) { float v = psm[r][k]; s3 = fmaf(v, v, s3); }
        float inv3 = 1.0f / sqrtf(s3);
#pragma unroll
        for (int k = 48; k < 64; k++) psm[r][k] *= inv3;
    }
    __syncthreads();

    const int nf = is_query ? 66 : 65;
    for (int i = tid; i < nf * 64; i += 256) {
        int k = i >> 6, r = i & 63;
        featT[(size_t)k * fstride + row0 + r] = psm[r][k];
    }
}

// ---------------------------------------------------------------------------
// Weight-MLP layer 1: relu(x_q @ W1.T + b1) -> g_qy [512][32]
// ---------------------------------------------------------------------------
__global__ __launch_bounds__(256) void mlp32_kernel(
    const float* __restrict__ X, const float* __restrict__ W1,
    const float* __restrict__ b1, float* __restrict__ Y)
{
    __shared__ __align__(16) float xs[16][68];
    __shared__ __align__(16) float ws[16][36];
    const int tid = threadIdx.x;
    const int r0 = (tid >> 3) * 2;   // 0..62 even
    const int d0 = (tid & 7) * 4;    // 0..28
    const int row0 = blockIdx.x * 64;
    const int lr = tid >> 2;
    const int lk = (tid & 3) * 4;

    float acc[2][4] = {};
    for (int k0 = 0; k0 < DIN; k0 += 16) {
        float4 xv = *(const float4*)(X + (size_t)(row0 + lr) * DIN + k0 + lk);
        float4 wv = make_float4(0.f, 0.f, 0.f, 0.f);
        if (tid < 128) wv = *(const float4*)(W1 + lr * DIN + k0 + lk);
        __syncthreads();
        xs[lk + 0][lr] = xv.x; xs[lk + 1][lr] = xv.y;
        xs[lk + 2][lr] = xv.z; xs[lk + 3][lr] = xv.w;
        if (tid < 128) {
            ws[lk + 0][lr] = wv.x; ws[lk + 1][lr] = wv.y;
            ws[lk + 2][lr] = wv.z; ws[lk + 3][lr] = wv.w;
        }
        __syncthreads();
#pragma unroll
        for (int kk = 0; kk < 16; kk++) {
            float a0 = xs[kk][r0];
            float a1 = xs[kk][r0 + 1];
            float4 b4 = *(const float4*)&ws[kk][d0];
            float bv[4] = {b4.x, b4.y, b4.z, b4.w};
#pragma unroll
            for (int j = 0; j < 4; j++) {
                acc[0][j] = fmaf(a0, bv[j], acc[0][j]);
                acc[1][j] = fmaf(a1, bv[j], acc[1][j]);
            }
        }
    }
#pragma unroll
    for (int i = 0; i < 2; i++)
#pragma unroll
        for (int j = 0; j < 4; j++)
            Y[(size_t)(row0 + r0 + i) * 32 + d0 + j] =
                fmaxf(acc[i][j] + b1[d0 + j], 0.f);
}

// ---------------------------------------------------------------------------
// Weight-MLP layer 2 + softplus -> g_qfeatT rows 66..68 (w1 scaled by ln2^2)
// ---------------------------------------------------------------------------
__global__ void wmlp_kernel(const float* __restrict__ Y,
                            const float* __restrict__ W2,
                            const float* __restrict__ b2,
                            float* __restrict__ qfT)
{
    int q = blockIdx.x * blockDim.x + threadIdx.x;
    if (q >= NQ) return;
    float z0 = b2[0], z1 = b2[1], z2 = b2[2];
#pragma unroll
    for (int k = 0; k < 32; k++) {
        float y = Y[q * 32 + k];
        z0 = fmaf(y, W2[k],      z0);
        z1 = fmaf(y, W2[32 + k], z1);
        z2 = fmaf(y, W2[64 + k], z2);
    }
    float sp0 = fmaxf(z0, 0.f) + log1pf(expf(-fabsf(z0)));
    float sp1 = fmaxf(z1, 0.f) + log1pf(expf(-fabsf(z1)));
    float sp2 = fmaxf(z2, 0.f) + log1pf(expf(-fabsf(z2)));
    qfT[(size_t)66 * NQ + q] = sp0;
    qfT[(size_t)67 * NQ + q] = sp1 * 0.4804530139182014f;  // fold ln2^2: d = ln2*lg2(ratio)
    qfT[(size_t)68 * NQ + q] = sp2;
}

// ---------------------------------------------------------------------------
// Pairwise kernel: 64q x 64c tile, 4x4 register tile, 3 fused K-phases
// Epilogue uses MUFU approx + Hastings acos poly (validated rel_err ~3.5e-7)
// ---------------------------------------------------------------------------
__global__ __launch_bounds__(256) void pair_kernel(
    const float* __restrict__ qfT, const float* __restrict__ cfT,
    float* __restrict__ out)
{
    __shared__ __align__(16) float qe[32][64], ce[32][64];
    __shared__ __align__(16) float qh[16][64], ch[16][64];
    __shared__ __align__(16) float qsm[16][64], csm[16][64];
    __shared__ float qxn[64], qbeta[64], qw0[64], qw1[64], qw2[64], cyn[64];

    const int tid = threadIdx.x;
    const int q0 = blockIdx.y * 64;
    const int c0 = blockIdx.x * 64;

    for (int i = tid; i < 64 * 64; i += 256) {
        int k = i >> 6, r = i & 63;
        float qv = qfT[(size_t)k * NQ + q0 + r];
        float cv = cfT[(size_t)k * NC + c0 + r];
        if (k < 32)      { qe[k][r] = qv;       ce[k][r] = cv; }
        else if (k < 48) { qh[k - 32][r] = qv;  ch[k - 32][r] = cv; }
        else             { qsm[k - 48][r] = qv; csm[k - 48][r] = cv; }
    }
    if (tid < 64) {
        int r = tid;
        qxn[r]   = qfT[(size_t)64 * NQ + q0 + r];
        qbeta[r] = qfT[(size_t)65 * NQ + q0 + r];
        qw0[r]   = qfT[(size_t)66 * NQ + q0 + r];
        qw1[r]   = qfT[(size_t)67 * NQ + q0 + r];
        qw2[r]   = qfT[(size_t)68 * NQ + q0 + r];
        cyn[r]   = cfT[(size_t)64 * NC + c0 + r];
    }
    __syncthreads();

    const int cq = (tid >> 4) * 4;   // query offset in tile
    const int cc = (tid & 15) * 4;   // corpus offset in tile

    float w0r[4], w1r[4], w2r[4], xnr[4], nbr[4], bbr[4], ynr[4];
#pragma unroll
    for (int i = 0; i < 4; i++) {
        w0r[i] = qw0[cq + i]; w1r[i] = qw1[cq + i]; w2r[i] = qw2[cq + i];
        xnr[i] = qxn[cq + i];
        float b = qbeta[cq + i];
        nbr[i] = -2.f * b;
        bbr[i] = b * b;
    }
#pragma unroll
    for (int j = 0; j < 4; j++) ynr[j] = cyn[cc + j];

    float tot[4][4];
    float acc[4][4];

    // ---- phase e: dist_e = 2 - 2*dot ----
#pragma unroll
    for (int i = 0; i < 4; i++)
#pragma unroll
        for (int j = 0; j < 4; j++) acc[i][j] = 0.f;
#pragma unroll
    for (int k = 0; k < 32; k++) {
        float4 a4 = *(const float4*)&qe[k][cq];
        float4 b4 = *(const float4*)&ce[k][cc];
        float av[4] = {a4.x, a4.y, a4.z, a4.w};
        float bv[4] = {b4.x, b4.y, b4.z, b4.w};
#pragma unroll
        for (int i = 0; i < 4; i++)
#pragma unroll
            for (int j = 0; j < 4; j++)
                acc[i][j] = fmaf(av[i], bv[j], acc[i][j]);
    }
#pragma unroll
    for (int i = 0; i < 4; i++)
#pragma unroll
        for (int j = 0; j < 4; j++)
            tot[i][j] = w0r[i] * (2.f - 2.f * acc[i][j]);

    // ---- phase h: hyperbolic dist^2 via lg2 (ln2^2 folded into w1) ----
#pragma unroll
    for (int i = 0; i < 4; i++)
#pragma unroll
        for (int j = 0; j < 4; j++) acc[i][j] = 0.f;
#pragma unroll
    for (int k = 0; k < 16; k++) {
        float4 a4 = *(const float4*)&qh[k][cq];
        float4 b4 = *(const float4*)&ch[k][cc];
        float av[4] = {a4.x, a4.y, a4.z, a4.w};
        float bv[4] = {b4.x, b4.y, b4.z, b4.w};
#pragma unroll
        for (int i = 0; i < 4; i++)
#pragma unroll
            for (int j = 0; j < 4; j++)
                acc[i][j] = fmaf(av[i], bv[j], acc[i][j]);
    }
#pragma unroll
    for (int i = 0; i < 4; i++) {
        const float xn = xnr[i], nb = nbr[i], bb = bbr[i];
#pragma unroll
        for (int j = 0; j < 4; j++) {
            float dh = acc[i][j];
            float yn = ynr[j];
            float s1 = fmaf(-2.f, dh, 1.f);                 // 1 - 2*dot
            float alpha = s1 + yn;
            float num = fmaf(alpha, fmaf(alpha, xn, nb * dh), bb * yn);
            float den = fmaxf(fmaf(xn, yn, s1), 1e-15f);
            float t = f_sqrt(fmaxf(num, 0.f)) * f_rcp(den);
            t = fminf(t, 0.99999994f);
            float L = f_lg2((1.f + t) * f_rcp(1.f - t));    // 2*atanh(t)/ln2
            tot[i][j] = fmaf(w1r[i], L * L, tot[i][j]);
        }
    }

    // ---- phase s: arccos(dot)^2 via Hastings poly ----
#pragma unroll
    for (int i = 0; i < 4; i++)
#pragma unroll
        for (int j = 0; j < 4; j++) acc[i][j] = 0.f;
#pragma unroll
    for (int k = 0; k < 16; k++) {
        float4 a4 = *(const float4*)&qsm[k][cq];
        float4 b4 = *(const float4*)&csm[k][cc];
        float av[4] = {a4.x, a4.y, a4.z, a4.w};
        float bv[4] = {b4.x, b4.y, b4.z, b4.w};
#pragma unroll
        for (int i = 0; i < 4; i++)
#pragma unroll
            for (int j = 0; j < 4; j++)
                acc[i][j] = fmaf(av[i], bv[j], acc[i][j]);
    }
#pragma unroll
    for (int i = 0; i < 4; i++)
#pragma unroll
        for (int j = 0; j < 4; j++) {
            float d = acc[i][j];
            float ad = fminf(fabsf(d), 1.f);
            float sq = f_sqrt(fmaxf(1.f - ad, 0.f));
            float p = -0.0012624911f;
            p = fmaf(p, ad,  0.0066700901f);
            p = fmaf(p, ad, -0.0170881256f);
            p = fmaf(p, ad,  0.0308918810f);
            p = fmaf(p, ad, -0.0501743046f);
            p = fmaf(p, ad,  0.0889789874f);
            p = fmaf(p, ad, -0.2145988016f);
            p = fmaf(p, ad,  1.5707963050f);
            float r = sq * p;                         // acos(|d|)
            float a = (d >= 0.f) ? r : 3.14159265358979f - r;
            tot[i][j] = fmaf(w2r[i], a * a, tot[i][j]);
        }

    // ---- store -total ----
#pragma unroll
    for (int i = 0; i < 4; i++) {
        float4 o;
        o.x = -tot[i][0]; o.y = -tot[i][1]; o.z = -tot[i][2]; o.w = -tot[i][3];
        *(float4*)(out + (size_t)(q0 + cq + i) * NC + c0 + cc) = o;
    }
}

// ---------------------------------------------------------------------------
extern "C" void kernel_launch(void* const* d_in, const int* in_sizes, int n_in,
                              void* d_out, int out_size)
{
    const float* x_q  = (const float*)d_in[0];
    const float* x_c  = (const float*)d_in[1];
    const float* We   = (const float*)d_in[2];
    const float* be   = (const float*)d_in[3];
    const float* Wh   = (const float*)d_in[4];
    const float* bh   = (const float*)d_in[5];
    const float* Ws   = (const float*)d_in[6];
    const float* bs   = (const float*)d_in[7];
    const float* scl  = (const float*)d_in[8];
    const float* W1   = (const float*)d_in[9];
    const float* b1   = (const float*)d_in[10];
    const float* W2   = (const float*)d_in[11];
    const float* b2   = (const float*)d_in[12];
    float* out = (float*)d_out;

    float *cfT, *qfT, *qy;
    cudaGetSymbolAddress((void**)&cfT, g_cfeatT);
    cudaGetSymbolAddress((void**)&qfT, g_qfeatT);
    cudaGetSymbolAddress((void**)&qy,  g_qy);

    proj64_kernel<<<NC / 64, 256>>>(x_c, We, be, Wh, bh, Ws, bs, scl, cfT, NC, 0);
    proj64_kernel<<<NQ / 64, 256>>>(x_q, We, be, Wh, bh, Ws, bs, scl, qfT, NQ, 1);
    mlp32_kernel<<<NQ / 64, 256>>>(x_q, W1, b1, qy);
    wmlp_kernel<<<2, 256>>>(qy, W2, b2, qfT);
    pair_kernel<<<dim3(NC / 64, NQ / 64), 256>>>(qfT, cfT, out);
}

// round 5
// speedup vs baseline: 1.8600x; 1.1140x over previous
#include <cuda_runtime.h>
#include <math.h>

#define NQ 512
#define NC 65536
#define DIN 768

// Scratch (static device globals).
// Corpus: hi-plane rows 0..63 (tf32-valued), row 64 = yn
__device__ float g_cfeatT[65 * NC];
__device__ float g_cfeatLo[64 * NC];
// Query: hi rows 0..63, 64 xn, 65 beta, 66 w0, 67 w1*ln2^2, 68 w2
__device__ float g_qfeatT[69 * NQ];
__device__ float g_qfeatLo[64 * NQ];
// Hidden relu layer for weight MLP
__device__ float g_qy[NQ * 32];

// ---------------- helpers ----------------
__device__ __forceinline__ float f_rcp(float x)  { float r; asm("rcp.approx.f32 %0,%1;"  : "=f"(r) : "f"(x)); return r; }
__device__ __forceinline__ float f_sqrt(float x) { float r; asm("sqrt.approx.f32 %0,%1;" : "=f"(r) : "f"(x)); return r; }
__device__ __forceinline__ float f_lg2(float x)  { float r; asm("lg2.approx.f32 %0,%1;"  : "=f"(r) : "f"(x)); return r; }
__device__ __forceinline__ float tf32_rna(float x) {
    unsigned u; asm("cvt.rna.tf32.f32 %0,%1;" : "=r"(u) : "f"(x)); return __uint_as_float(u);
}
__device__ __forceinline__ void mma_tf32(float c[4], const unsigned a[4], const unsigned b[2]) {
    asm volatile(
        "mma.sync.aligned.m16n8k8.row.col.f32.tf32.tf32.f32 "
        "{%0,%1,%2,%3},{%4,%5,%6,%7},{%8,%9},{%0,%1,%2,%3};"
        : "+f"(c[0]), "+f"(c[1]), "+f"(c[2]), "+f"(c[3])
        : "r"(a[0]), "r"(a[1]), "r"(a[2]), "r"(a[3]), "r"(b[0]), "r"(b[1]));
}

// ---------------------------------------------------------------------------
// Projection kernel: 64 rows x 64 dims tile, prefetched K-chunked GEMM.
// Epilogue emits tf32 hi/lo split planes.
// ---------------------------------------------------------------------------
__global__ __launch_bounds__(256) void proj64_kernel(
    const float* __restrict__ X,
    const float* __restrict__ We, const float* __restrict__ be,
    const float* __restrict__ Wh, const float* __restrict__ bh,
    const float* __restrict__ Ws, const float* __restrict__ bs,
    const float* __restrict__ scale_p,
    float* __restrict__ featT, float* __restrict__ featLo,
    int fstride, int is_query)
{
    __shared__ __align__(16) float xs[16][68];
    __shared__ __align__(16) float ws[16][68];
    __shared__ __align__(16) float psm[64][68];

    const int tid = threadIdx.x;
    const int r0 = (tid >> 4) * 4;
    const int d0 = (tid & 15) * 4;
    const int row0 = blockIdx.x * 64;

    const int lr = tid >> 2;
    const int lk = (tid & 3) * 4;

    const float* Xp = X + (size_t)(row0 + lr) * DIN + lk;
    const float* Wp;
    if (lr < 32)      Wp = We + lr * DIN + lk;
    else if (lr < 48) Wp = Wh + (lr - 32) * DIN + lk;
    else              Wp = Ws + (lr - 48) * DIN + lk;

    float acc[4][4] = {};

    float4 xv = *(const float4*)(Xp);
    float4 wv = *(const float4*)(Wp);

    for (int k0 = 0; k0 < DIN; k0 += 16) {
        __syncthreads();
        xs[lk + 0][lr] = xv.x; xs[lk + 1][lr] = xv.y;
        xs[lk + 2][lr] = xv.z; xs[lk + 3][lr] = xv.w;
        ws[lk + 0][lr] = wv.x; ws[lk + 1][lr] = wv.y;
        ws[lk + 2][lr] = wv.z; ws[lk + 3][lr] = wv.w;
        __syncthreads();
        if (k0 + 16 < DIN) {
            xv = *(const float4*)(Xp + k0 + 16);
            wv = *(const float4*)(Wp + k0 + 16);
        }
#pragma unroll
        for (int kk = 0; kk < 16; kk++) {
            float4 a4 = *(const float4*)&xs[kk][r0];
            float4 b4 = *(const float4*)&ws[kk][d0];
            float av[4] = {a4.x, a4.y, a4.z, a4.w};
            float bv[4] = {b4.x, b4.y, b4.z, b4.w};
#pragma unroll
            for (int i = 0; i < 4; i++)
#pragma unroll
                for (int j = 0; j < 4; j++)
                    acc[i][j] = fmaf(av[i], bv[j], acc[i][j]);
        }
    }
    __syncthreads();
#pragma unroll
    for (int i = 0; i < 4; i++)
#pragma unroll
        for (int j = 0; j < 4; j++) {
            int d = d0 + j;
            float bias = (d < 32) ? be[d] : (d < 48) ? bh[d - 32] : bs[d - 48];
            psm[r0 + i][d] = acc[i][j] + bias;
        }
    __syncthreads();

    if (tid < 64) {
        const int r = tid;
        const float sc = *scale_p;
        float s2 = 0.f;
#pragma unroll
        for (int k = 0; k < 32; k++) { float v = psm[r][k]; s2 = fmaf(v, v, s2); }
        float inv = 1.0f / sqrtf(s2);
#pragma unroll
        for (int k = 0; k < 32; k++) psm[r][k] *= inv;
        float h2 = 0.f;
#pragma unroll
        for (int k = 32; k < 48; k++) { float v = psm[r][k] * sc; psm[r][k] = v; h2 = fmaf(v, v, h2); }
        float n  = fmaxf(sqrtf(h2), 1e-15f);
        float th = tanhf(n);
        float fac = th / n;
#pragma unroll
        for (int k = 32; k < 48; k++) psm[r][k] *= fac;
        psm[r][64] = th * th;                       // yn / xn
        if (is_query) psm[r][65] = 1.0f - th * th;  // beta
        float s3 = 0.f;
#pragma unroll
        for (int k = 48; k < 64; k++) { float v = psm[r][k]; s3 = fmaf(v, v, s3); }
        float inv3 = 1.0f / sqrtf(s3);
#pragma unroll
        for (int k = 48; k < 64; k++) psm[r][k] *= inv3;
    }
    __syncthreads();

    // features: hi/lo tf32 split
    for (int i = tid; i < 64 * 64; i += 256) {
        int k = i >> 6, r = i & 63;
        float v = psm[r][k];
        float hi = tf32_rna(v);
        float lo = tf32_rna(v - hi);
        featT [(size_t)k * fstride + row0 + r] = hi;
        featLo[(size_t)k * fstride + row0 + r] = lo;
    }
    // params (row 64, and 65 for queries)
    const int np = is_query ? 2 : 1;
    for (int i = tid; i < np * 64; i += 256) {
        int k = 64 + (i >> 6), r = i & 63;
        featT[(size_t)k * fstride + row0 + r] = psm[r][k];
    }
}

// ---------------------------------------------------------------------------
// Weight-MLP layer 1: relu(x_q @ W1.T + b1) -> g_qy [512][32]
// ---------------------------------------------------------------------------
__global__ __launch_bounds__(256) void mlp32_kernel(
    const float* __restrict__ X, const float* __restrict__ W1,
    const float* __restrict__ b1, float* __restrict__ Y)
{
    __shared__ __align__(16) float xs[16][68];
    __shared__ __align__(16) float ws[16][36];
    const int tid = threadIdx.x;
    const int r0 = (tid >> 3) * 2;
    const int d0 = (tid & 7) * 4;
    const int row0 = blockIdx.x * 64;
    const int lr = tid >> 2;
    const int lk = (tid & 3) * 4;

    float acc[2][4] = {};
    for (int k0 = 0; k0 < DIN; k0 += 16) {
        float4 xv = *(const float4*)(X + (size_t)(row0 + lr) * DIN + k0 + lk);
        float4 wv = make_float4(0.f, 0.f, 0.f, 0.f);
        if (tid < 128) wv = *(const float4*)(W1 + lr * DIN + k0 + lk);
        __syncthreads();
        xs[lk + 0][lr] = xv.x; xs[lk + 1][lr] = xv.y;
        xs[lk + 2][lr] = xv.z; xs[lk + 3][lr] = xv.w;
        if (tid < 128) {
            ws[lk + 0][lr] = wv.x; ws[lk + 1][lr] = wv.y;
            ws[lk + 2][lr] = wv.z; ws[lk + 3][lr] = wv.w;
        }
        __syncthreads();
#pragma unroll
        for (int kk = 0; kk < 16; kk++) {
            float a0 = xs[kk][r0];
            float a1 = xs[kk][r0 + 1];
            float4 b4 = *(const float4*)&ws[kk][d0];
            float bv[4] = {b4.x, b4.y, b4.z, b4.w};
#pragma unroll
            for (int j = 0; j < 4; j++) {
                acc[0][j] = fmaf(a0, bv[j], acc[0][j]);
                acc[1][j] = fmaf(a1, bv[j], acc[1][j]);
            }
        }
    }
#pragma unroll
    for (int i = 0; i < 2; i++)
#pragma unroll
        for (int j = 0; j < 4; j++)
            Y[(size_t)(row0 + r0 + i) * 32 + d0 + j] =
                fmaxf(acc[i][j] + b1[d0 + j], 0.f);
}

// ---------------------------------------------------------------------------
// Weight-MLP layer 2 + softplus -> g_qfeatT rows 66..68 (w1 scaled by ln2^2)
// ---------------------------------------------------------------------------
__global__ void wmlp_kernel(const float* __restrict__ Y,
                            const float* __restrict__ W2,
                            const float* __restrict__ b2,
                            float* __restrict__ qfT)
{
    int q = blockIdx.x * blockDim.x + threadIdx.x;
    if (q >= NQ) return;
    float z0 = b2[0], z1 = b2[1], z2 = b2[2];
#pragma unroll
    for (int k = 0; k < 32; k++) {
        float y = Y[q * 32 + k];
        z0 = fmaf(y, W2[k],      z0);
        z1 = fmaf(y, W2[32 + k], z1);
        z2 = fmaf(y, W2[64 + k], z2);
    }
    float sp0 = fmaxf(z0, 0.f) + log1pf(expf(-fabsf(z0)));
    float sp1 = fmaxf(z1, 0.f) + log1pf(expf(-fabsf(z1)));
    float sp2 = fmaxf(z2, 0.f) + log1pf(expf(-fabsf(z2)));
    qfT[(size_t)66 * NQ + q] = sp0;
    qfT[(size_t)67 * NQ + q] = sp1 * 0.4804530139182014f;  // fold ln2^2
    qfT[(size_t)68 * NQ + q] = sp2;
}

// ---------------------------------------------------------------------------
// Pairwise kernel: 64q x 128c per CTA, 8 warps of 32x32, tf32 MMA split hi/lo
// ---------------------------------------------------------------------------
__global__ __launch_bounds__(256, 2) void pair_kernel(
    const float* __restrict__ qfT, const float* __restrict__ qfLo,
    const float* __restrict__ cfT, const float* __restrict__ cfLo,
    float* __restrict__ out)
{
    __shared__ __align__(16) float sqh[16][68], sql[16][68];
    __shared__ __align__(16) float sch[16][132], sclo[16][132];
    __shared__ float qxn[64], qbt[64], qw0[64], qw1[64], qw2[64], cyn[128];

    const int tid  = threadIdx.x;
    const int lane = tid & 31;
    const int warp = tid >> 5;
    const int gid  = lane >> 2;     // 0..7
    const int tig  = lane & 3;      // 0..3
    const int qw   = (warp >> 2) * 32;   // warp q-origin (0 or 32)
    const int cw   = (warp & 3) * 32;    // warp c-origin (0,32,64,96)

    const int q0 = blockIdx.y * 64;
    const int c0 = blockIdx.x * 128;

    // ---- params ----
    if (tid < 64) {
        qxn[tid] = qfT[(size_t)64 * NQ + q0 + tid];
        qbt[tid] = qfT[(size_t)65 * NQ + q0 + tid];
        qw0[tid] = qfT[(size_t)66 * NQ + q0 + tid];
        qw1[tid] = qfT[(size_t)67 * NQ + q0 + tid];
        qw2[tid] = qfT[(size_t)68 * NQ + q0 + tid];
    } else if (tid < 192) {
        const int r = tid - 64;
        cyn[r] = cfT[(size_t)64 * NC + c0 + r];
    }

    auto stage = [&](int off) {
        {   // q planes: 16 rows x 64 = 256 float4 (hi) — one per thread
            const int row = tid >> 4;
            const int c4  = (tid & 15) * 4;
            *(float4*)&sqh[row][c4] = *(const float4*)(qfT  + (size_t)(off + row) * NQ + q0 + c4);
            *(float4*)&sql[row][c4] = *(const float4*)(qfLo + (size_t)(off + row) * NQ + q0 + c4);
        }
        // c planes: 16 rows x 128 = 512 float4 — two per thread
        for (int t = tid; t < 512; t += 256) {
            const int row = t >> 5;
            const int c4  = (t & 31) * 4;
            *(float4*)&sch [row][c4] = *(const float4*)(cfT  + (size_t)(off + row) * NC + c0 + c4);
            *(float4*)&sclo[row][c4] = *(const float4*)(cfLo + (size_t)(off + row) * NC + c0 + c4);
        }
    };

    auto seg_mma = [&](float acc[8][4]) {
#pragma unroll
        for (int kc = 0; kc < 2; kc++) {
            const int k0 = kc * 8;
            unsigned bh[4][2], bl[4][2];
#pragma unroll
            for (int ct = 0; ct < 4; ct++) {
                const int cc = cw + ct * 8 + gid;
                bh[ct][0] = __float_as_uint(sch [k0 + tig][cc]);
                bh[ct][1] = __float_as_uint(sch [k0 + tig + 4][cc]);
                bl[ct][0] = __float_as_uint(sclo[k0 + tig][cc]);
                bl[ct][1] = __float_as_uint(sclo[k0 + tig + 4][cc]);
            }
#pragma unroll
            for (int qt = 0; qt < 2; qt++) {
                const int r = qw + qt * 16 + gid;
                unsigned ah[4], al[4];
                ah[0] = __float_as_uint(sqh[k0 + tig][r]);
                ah[1] = __float_as_uint(sqh[k0 + tig][r + 8]);
                ah[2] = __float_as_uint(sqh[k0 + tig + 4][r]);
                ah[3] = __float_as_uint(sqh[k0 + tig + 4][r + 8]);
                al[0] = __float_as_uint(sql[k0 + tig][r]);
                al[1] = __float_as_uint(sql[k0 + tig][r + 8]);
                al[2] = __float_as_uint(sql[k0 + tig + 4][r]);
                al[3] = __float_as_uint(sql[k0 + tig + 4][r + 8]);
#pragma unroll
                for (int ct = 0; ct < 4; ct++) {
                    float* a = acc[qt * 4 + ct];
                    mma_tf32(a, ah, bh[ct]);
                    mma_tf32(a, ah, bl[ct]);
                    mma_tf32(a, al, bh[ct]);
                }
            }
        }
    };

    float tot[8][4];
    float acc[8][4];

    // ================= phase e (k rows 0..31, two 16-row segments) =========
#pragma unroll
    for (int t = 0; t < 8; t++)
#pragma unroll
        for (int m = 0; m < 4; m++) acc[t][m] = 0.f;
    stage(0);
    __syncthreads();
    seg_mma(acc);
    __syncthreads();
    stage(16);
    __syncthreads();
    seg_mma(acc);
#pragma unroll
    for (int qt = 0; qt < 2; qt++) {
        const int lqA = qw + qt * 16 + gid;
        const float wA = qw0[lqA], wB = qw0[lqA + 8];
#pragma unroll
        for (int ct = 0; ct < 4; ct++) {
            const int t = qt * 4 + ct;
            tot[t][0] = wA * (2.f - 2.f * acc[t][0]);
            tot[t][1] = wA * (2.f - 2.f * acc[t][1]);
            tot[t][2] = wB * (2.f - 2.f * acc[t][2]);
            tot[t][3] = wB * (2.f - 2.f * acc[t][3]);
        }
    }

    // ================= phase h (k rows 32..47) =============================
#pragma unroll
    for (int t = 0; t < 8; t++)
#pragma unroll
        for (int m = 0; m < 4; m++) acc[t][m] = 0.f;
    __syncthreads();
    stage(32);
    __syncthreads();
    seg_mma(acc);
#pragma unroll
    for (int qt = 0; qt < 2; qt++) {
        const int lqA = qw + qt * 16 + gid;
#pragma unroll
        for (int half = 0; half < 2; half++) {
            const int lq = lqA + half * 8;
            const float xn = qxn[lq];
            const float bt = qbt[lq];
            const float nb = -2.f * bt;
            const float bb = bt * bt;
            const float w1 = qw1[lq];
#pragma unroll
            for (int ct = 0; ct < 4; ct++) {
                const int t = qt * 4 + ct;
                const int lc = cw + ct * 8 + 2 * tig;
#pragma unroll
                for (int m = 0; m < 2; m++) {
                    const float dh = acc[t][half * 2 + m];
                    const float yn = cyn[lc + m];
                    float s1 = fmaf(-2.f, dh, 1.f);
                    float alpha = s1 + yn;
                    float num = fmaf(alpha, fmaf(alpha, xn, nb * dh), bb * yn);
                    float den = fmaxf(fmaf(xn, yn, s1), 1e-15f);
                    float tv = f_sqrt(fmaxf(num, 0.f)) * f_rcp(den);
                    tv = fminf(tv, 0.99999994f);
                    float L = f_lg2((1.f + tv) * f_rcp(1.f - tv));
                    tot[t][half * 2 + m] = fmaf(w1, L * L, tot[t][half * 2 + m]);
                }
            }
        }
    }

    // ================= phase s (k rows 48..63) =============================
#pragma unroll
    for (int t = 0; t < 8; t++)
#pragma unroll
        for (int m = 0; m < 4; m++) acc[t][m] = 0.f;
    __syncthreads();
    stage(48);
    __syncthreads();
    seg_mma(acc);
#pragma unroll
    for (int qt = 0; qt < 2; qt++) {
        const int lqA = qw + qt * 16 + gid;
#pragma unroll
        for (int half = 0; half < 2; half++) {
            const int lq = lqA + half * 8;
            const float w2 = qw2[lq];
#pragma unroll
            for (int ct = 0; ct < 4; ct++) {
                const int t = qt * 4 + ct;
#pragma unroll
                for (int m = 0; m < 2; m++) {
                    const float d = acc[t][half * 2 + m];
                    float ad = fminf(fabsf(d), 1.f);
                    float sq = f_sqrt(fmaxf(1.f - ad, 0.f));
                    float p = -0.0012624911f;
                    p = fmaf(p, ad,  0.0066700901f);
                    p = fmaf(p, ad, -0.0170881256f);
                    p = fmaf(p, ad,  0.0308918810f);
                    p = fmaf(p, ad, -0.0501743046f);
                    p = fmaf(p, ad,  0.0889789874f);
                    p = fmaf(p, ad, -0.2145988016f);
                    p = fmaf(p, ad,  1.5707963050f);
                    float r = sq * p;
                    float a = (d >= 0.f) ? r : 3.14159265358979f - r;
                    tot[t][half * 2 + m] = fmaf(w2, a * a, tot[t][half * 2 + m]);
                }
            }
        }
    }

    // ================= store -total ========================================
#pragma unroll
    for (int qt = 0; qt < 2; qt++) {
        const int lqA = qw + qt * 16 + gid;
#pragma unroll
        for (int ct = 0; ct < 4; ct++) {
            const int t = qt * 4 + ct;
            const int lc = cw + ct * 8 + 2 * tig;
            float2 oA = make_float2(-tot[t][0], -tot[t][1]);
            float2 oB = make_float2(-tot[t][2], -tot[t][3]);
            *(float2*)(out + (size_t)(q0 + lqA) * NC + c0 + lc)     = oA;
            *(float2*)(out + (size_t)(q0 + lqA + 8) * NC + c0 + lc) = oB;
        }
    }
}

// ---------------------------------------------------------------------------
extern "C" void kernel_launch(void* const* d_in, const int* in_sizes, int n_in,
                              void* d_out, int out_size)
{
    const float* x_q  = (const float*)d_in[0];
    const float* x_c  = (const float*)d_in[1];
    const float* We   = (const float*)d_in[2];
    const float* be   = (const float*)d_in[3];
    const float* Wh   = (const float*)d_in[4];
    const float* bh   = (const float*)d_in[5];
    const float* Ws   = (const float*)d_in[6];
    const float* bs   = (const float*)d_in[7];
    const float* scl  = (const float*)d_in[8];
    const float* W1   = (const float*)d_in[9];
    const float* b1   = (const float*)d_in[10];
    const float* W2   = (const float*)d_in[11];
    const float* b2   = (const float*)d_in[12];
    float* out = (float*)d_out;

    float *cfT, *cfLo, *qfT, *qfLo, *qy;
    cudaGetSymbolAddress((void**)&cfT,  g_cfeatT);
    cudaGetSymbolAddress((void**)&cfLo, g_cfeatLo);
    cudaGetSymbolAddress((void**)&qfT,  g_qfeatT);
    cudaGetSymbolAddress((void**)&qfLo, g_qfeatLo);
    cudaGetSymbolAddress((void**)&qy,   g_qy);

    proj64_kernel<<<NC / 64, 256>>>(x_c, We, be, Wh, bh, Ws, bs, scl, cfT, cfLo, NC, 0);
    proj64_kernel<<<NQ / 64, 256>>>(x_q, We, be, Wh, bh, Ws, bs, scl, qfT, qfLo, NQ, 1);
    mlp32_kernel<<<NQ / 64, 256>>>(x_q, W1, b1, qy);
    wmlp_kernel<<<2, 256>>>(qy, W2, b2, qfT);
    pair_kernel<<<dim3(NC / 128, NQ / 64), 256>>>(qfT, qfLo, cfT, cfLo, out);
}